// round 3
// baseline (speedup 1.0000x reference)
#include <cuda_runtime.h>
#include <cstdint>

// ---------------------------------------------------------------------------
// Problem constants
// ---------------------------------------------------------------------------
#define T_STEPS 2048
#define BATCH   64
#define INSZ    512
#define HID     256
#define G4      1024      // 4*HID
#define OUTSZ   128
#define MROWS   (T_STEPS * BATCH)   // 131072

// Scratch (device globals: allocation-free per harness rules)
__device__ float g_Xp[(size_t)MROWS * G4];   // input projection + biases
__device__ float g_hs[(size_t)MROWS * HID];  // hidden states

// ---------------------------------------------------------------------------
// Packed fp32x2 FMA (SASS FFMA2): d = a*b + d elementwise on 2 floats.
// ---------------------------------------------------------------------------
__device__ __forceinline__ void ffma2(float2& d, const float2& a, const float2& b)
{
    asm("fma.rn.f32x2 %0, %1, %2, %0;"
        : "+l"(reinterpret_cast<unsigned long long&>(d))
        : "l"(reinterpret_cast<const unsigned long long&>(a)),
          "l"(reinterpret_cast<const unsigned long long&>(b)));
}

// ---------------------------------------------------------------------------
// GEMM (NT): C[m,n] = sum_k A[m,k] * B[n,k] + bias1[n] (+ bias2[n])
// BM=BN=128, BK=16, 256 threads, 8x8 micro-tile computed as 8x4 f32x2 packs.
// A tile stored DUPLICATED in smem so float4 loads yield (a,a) packs directly.
// ---------------------------------------------------------------------------
__global__ void __launch_bounds__(256)
sgemm128(const float* __restrict__ A, const float* __restrict__ Bm,
         const float* __restrict__ bias1, const float* __restrict__ bias2,
         float* __restrict__ C, int K, int N)
{
    __shared__ float As2[16][260];   // duplicated A tile, padded
    __shared__ float Bs[16][128];

    const int tid = threadIdx.x;
    const int tx = tid & 15;
    const int ty = tid >> 4;
    const size_t m0 = (size_t)blockIdx.x * 128;
    const int n0 = blockIdx.y * 128;

    const int lrow = tid >> 2;        // 0..63
    const int lk   = (tid & 3) * 4;   // 0,4,8,12

    const float* Ar0 = A  + (m0 + lrow) * (size_t)K + lk;
    const float* Ar1 = Ar0 + (size_t)64 * K;
    const float* Br0 = Bm + (size_t)(n0 + lrow) * K + lk;
    const float* Br1 = Br0 + (size_t)64 * K;

    float2 acc[8][4];
#pragma unroll
    for (int i = 0; i < 8; ++i)
#pragma unroll
        for (int j = 0; j < 4; ++j) acc[i][j] = make_float2(0.f, 0.f);

    for (int k0 = 0; k0 < K; k0 += 16) {
        float4 a0 = *(const float4*)(Ar0 + k0);
        float4 a1 = *(const float4*)(Ar1 + k0);
        float4 b0 = *(const float4*)(Br0 + k0);
        float4 b1 = *(const float4*)(Br1 + k0);
        __syncthreads();
        // duplicated A stores: As2[k][2r] = As2[k][2r+1] = A[r][k]
        *(float2*)&As2[lk+0][2*lrow]     = make_float2(a0.x, a0.x);
        *(float2*)&As2[lk+1][2*lrow]     = make_float2(a0.y, a0.y);
        *(float2*)&As2[lk+2][2*lrow]     = make_float2(a0.z, a0.z);
        *(float2*)&As2[lk+3][2*lrow]     = make_float2(a0.w, a0.w);
        *(float2*)&As2[lk+0][2*lrow+128] = make_float2(a1.x, a1.x);
        *(float2*)&As2[lk+1][2*lrow+128] = make_float2(a1.y, a1.y);
        *(float2*)&As2[lk+2][2*lrow+128] = make_float2(a1.z, a1.z);
        *(float2*)&As2[lk+3][2*lrow+128] = make_float2(a1.w, a1.w);
        Bs[lk+0][lrow]    = b0.x; Bs[lk+1][lrow]    = b0.y;
        Bs[lk+2][lrow]    = b0.z; Bs[lk+3][lrow]    = b0.w;
        Bs[lk+0][lrow+64] = b1.x; Bs[lk+1][lrow+64] = b1.y;
        Bs[lk+2][lrow+64] = b1.z; Bs[lk+3][lrow+64] = b1.w;
        __syncthreads();
#pragma unroll
        for (int kk = 0; kk < 16; ++kk) {
            float2 ad[8];
            float4 t;
            t = *(const float4*)&As2[kk][8*ty];
            ad[0] = make_float2(t.x, t.y); ad[1] = make_float2(t.z, t.w);
            t = *(const float4*)&As2[kk][8*ty + 4];
            ad[2] = make_float2(t.x, t.y); ad[3] = make_float2(t.z, t.w);
            t = *(const float4*)&As2[kk][8*ty + 128];
            ad[4] = make_float2(t.x, t.y); ad[5] = make_float2(t.z, t.w);
            t = *(const float4*)&As2[kk][8*ty + 132];
            ad[6] = make_float2(t.x, t.y); ad[7] = make_float2(t.z, t.w);
            float2 bp[4];
            float4 u = *(const float4*)&Bs[kk][tx*4];
            bp[0] = make_float2(u.x, u.y); bp[1] = make_float2(u.z, u.w);
            u = *(const float4*)&Bs[kk][tx*4 + 64];
            bp[2] = make_float2(u.x, u.y); bp[3] = make_float2(u.z, u.w);
#pragma unroll
            for (int i = 0; i < 8; ++i)
#pragma unroll
                for (int j = 0; j < 4; ++j)
                    ffma2(acc[i][j], ad[i], bp[j]);
        }
    }

    // bias
    float4 bb0 = *(const float4*)(bias1 + n0 + tx * 4);
    float4 bb1 = *(const float4*)(bias1 + n0 + tx * 4 + 64);
    if (bias2) {
        float4 c0 = *(const float4*)(bias2 + n0 + tx * 4);
        float4 c1 = *(const float4*)(bias2 + n0 + tx * 4 + 64);
        bb0.x += c0.x; bb0.y += c0.y; bb0.z += c0.z; bb0.w += c0.w;
        bb1.x += c1.x; bb1.y += c1.y; bb1.z += c1.z; bb1.w += c1.w;
    }

#pragma unroll
    for (int i = 0; i < 8; ++i) {
        size_t row = m0 + ty * 4 + (i < 4 ? i : 60 + i);
        float4 o0 = make_float4(acc[i][0].x + bb0.x, acc[i][0].y + bb0.y,
                                acc[i][1].x + bb0.z, acc[i][1].y + bb0.w);
        float4 o1 = make_float4(acc[i][2].x + bb1.x, acc[i][2].y + bb1.y,
                                acc[i][3].x + bb1.z, acc[i][3].y + bb1.w);
        *(float4*)(C + row * N + n0 + tx * 4)      = o0;
        *(float4*)(C + row * N + n0 + tx * 4 + 64) = o1;
    }
}

// ---------------------------------------------------------------------------
// LSTM recurrence: persistent clustered kernel, register-resident weights.
// 16 clusters x 8 CTAs x 256 threads. Cluster cl owns batches [cl*4, cl*4+4).
// CTA rank r owns 128 W_hh rows {g*256 + r*32 + jj : g in 0..3, jj in 0..31}.
// Thread (warp w, lane): rows lr = lane*4..lane*4+3, K chunk [w*32,(w+1)*32),
// weights held in 64 f32x2 registers. Accumulation uses K-pair packed FFMA2:
// acc = (sum over even k, sum over odd k); h loads are natural b64 packs.
// Cross-warp reduction in smem; h broadcast to 8 cluster CTAs via DSMEM.
// ---------------------------------------------------------------------------
__global__ void __launch_bounds__(256, 1)
lstm_rec_kernel(const float* __restrict__ Whh,
                const float* __restrict__ Xp,
                float* __restrict__ hs)
{
    __shared__ float hsm[2][4][256];    // double-buffered h, [buf][b][k]
    __shared__ float part[8][4][128];   // [warp][b][lr]
    __shared__ float hstage[128];       // [b*32 + jj]

    const int tid  = threadIdx.x;
    const int lane = tid & 31;
    const int w    = tid >> 5;

    unsigned r;
    asm("mov.u32 %0, %%cluster_ctarank;" : "=r"(r));
    const int cl = blockIdx.x >> 3;

    // Load this thread's weights into registers: 4 rows x 16 k-pairs.
    float2 wreg[4][16];
#pragma unroll
    for (int rr = 0; rr < 4; ++rr) {
        int lr = lane * 4 + rr;
        int grow = ((lr >> 5) << 8) + (int)r * 32 + (lr & 31);
        const float2* wp = (const float2*)(Whh + (size_t)grow * 256 + w * 32);
#pragma unroll
        for (int k2 = 0; k2 < 16; ++k2) wreg[rr][k2] = wp[k2];
    }
    for (int i = tid; i < 4 * 256; i += 256) ((float*)hsm)[i] = 0.f; // h0 = 0
    __syncthreads();

    const int bb = tid >> 5;   // for tid<128: batch 0..3
    const int jj = tid & 31;
    float c = 0.f;             // cell state register (tid<128)

    for (int t = 0; t < T_STEPS; ++t) {
        const int cur = t & 1;

        // Early-issue Xp loads (hidden behind the dot loop)
        float xq0 = 0.f, xq1 = 0.f, xq2 = 0.f, xq3 = 0.f;
        if (tid < 128) {
            const float* xp = Xp + ((size_t)t * 64 + cl * 4 + bb) * 1024
                                 + (int)r * 32 + jj;
            xq0 = xp[0]; xq1 = xp[256]; xq2 = xp[512]; xq3 = xp[768];
        }

        // Dot phase: 16 k-pairs x 4 rows x 4 batches of FFMA2.
        float2 acc[4][4];
#pragma unroll
        for (int rr = 0; rr < 4; ++rr)
#pragma unroll
            for (int b = 0; b < 4; ++b) acc[rr][b] = make_float2(0.f, 0.f);

        const float* hb = &hsm[cur][0][w * 32];
#pragma unroll
        for (int k2 = 0; k2 < 16; ++k2) {
            float2 h0 = *(const float2*)(hb + 2 * k2);
            float2 h1 = *(const float2*)(hb + 256 + 2 * k2);
            float2 h2 = *(const float2*)(hb + 512 + 2 * k2);
            float2 h3 = *(const float2*)(hb + 768 + 2 * k2);
#pragma unroll
            for (int rr = 0; rr < 4; ++rr) {
                ffma2(acc[rr][0], wreg[rr][k2], h0);
                ffma2(acc[rr][1], wreg[rr][k2], h1);
                ffma2(acc[rr][2], wreg[rr][k2], h2);
                ffma2(acc[rr][3], wreg[rr][k2], h3);
            }
        }
        // Horizontal add (even+odd K sums) and store partials.
#pragma unroll
        for (int b = 0; b < 4; ++b) {
            float4 v = make_float4(acc[0][b].x + acc[0][b].y,
                                   acc[1][b].x + acc[1][b].y,
                                   acc[2][b].x + acc[2][b].y,
                                   acc[3][b].x + acc[3][b].y);
            *(float4*)&part[w][b][lane * 4] = v;
        }
        __syncthreads();

        // Reduction + gates (tid<128: one (jj, bb) pair each)
        if (tid < 128) {
            float s0 = xq0, s1 = xq1, s2 = xq2, s3 = xq3;
#pragma unroll
            for (int w8 = 0; w8 < 8; ++w8) {
                const float* p = &part[w8][bb][jj];
                s0 += p[0]; s1 += p[32]; s2 += p[64]; s3 += p[96];
            }
            float ig = 1.f / (1.f + __expf(-s0));
            float fg = 1.f / (1.f + __expf(-s1));
            float e2 = __expf(2.f * s2);
            float gg = (e2 - 1.f) / (e2 + 1.f);
            float og = 1.f / (1.f + __expf(-s3));
            c = fg * c + ig * gg;
            float ec = __expf(2.f * c);
            float h = og * ((ec - 1.f) / (ec + 1.f));
            hstage[bb * 32 + jj] = h;
            hs[((size_t)t * 64 + cl * 4 + bb) * 256 + (int)r * 32 + jj] = h;
        }
        __syncthreads();

        // DSMEM push: broadcast this CTA's 128 new h values into every
        // cluster CTA's hsm[next]. One STS.128 per thread (8 dst x 32 f4).
        {
            const int nxt = cur ^ 1;
            const unsigned dst = (unsigned)(tid >> 5);   // 0..7
            const int q = tid & 31;                      // float4 idx over 128
            float4 v = ((const float4*)hstage)[q];
            float* dp = &hsm[nxt][q >> 3][(int)r * 32 + ((q & 7) << 2)];
            unsigned la = (unsigned)__cvta_generic_to_shared(dp);
            unsigned ra;
            asm volatile("mapa.shared::cluster.u32 %0, %1, %2;"
                         : "=r"(ra) : "r"(la), "r"(dst));
            asm volatile("st.shared::cluster.v4.f32 [%0], {%1,%2,%3,%4};"
                         :: "r"(ra), "f"(v.x), "f"(v.y), "f"(v.z), "f"(v.w)
                         : "memory");
        }
        asm volatile("barrier.cluster.arrive.aligned;" ::: "memory");
        asm volatile("barrier.cluster.wait.aligned;"   ::: "memory");
    }
}

// ---------------------------------------------------------------------------
// Launch
// ---------------------------------------------------------------------------
extern "C" void kernel_launch(void* const* d_in, const int* in_sizes, int n_in,
                              void* d_out, int out_size)
{
    const float* inputs = (const float*)d_in[0];
    const float* W_ih   = (const float*)d_in[1];
    const float* W_hh   = (const float*)d_in[2];
    const float* b_ih   = (const float*)d_in[3];
    const float* b_hh   = (const float*)d_in[4];
    const float* W_fc   = (const float*)d_in[5];
    const float* b_fc   = (const float*)d_in[6];
    float* out = (float*)d_out;

    float *Xp, *hsbuf;
    cudaGetSymbolAddress((void**)&Xp, g_Xp);
    cudaGetSymbolAddress((void**)&hsbuf, g_hs);

    // 1) Xp = inputs @ W_ih^T + (b_ih + b_hh)   [131072 x 1024]
    {
        dim3 grid(MROWS / 128, G4 / 128);
        sgemm128<<<grid, 256>>>(inputs, W_ih, b_ih, b_hh, Xp, INSZ, G4);
    }

    // 2) LSTM recurrence (clustered persistent kernel) -> hs [131072 x 256]
    {
        cudaLaunchConfig_t cfg = {};
        cfg.gridDim = dim3(128, 1, 1);
        cfg.blockDim = dim3(256, 1, 1);
        cfg.dynamicSmemBytes = 0;
        cfg.stream = 0;
        cudaLaunchAttribute attr[1];
        attr[0].id = cudaLaunchAttributeClusterDimension;
        attr[0].val.clusterDim.x = 8;
        attr[0].val.clusterDim.y = 1;
        attr[0].val.clusterDim.z = 1;
        cfg.attrs = attr;
        cfg.numAttrs = 1;
        cudaLaunchKernelEx(&cfg, lstm_rec_kernel, W_hh, (const float*)Xp, hsbuf);
    }

    // 3) out = hs @ W_fc^T + b_fc   [131072 x 128]
    {
        dim3 grid(MROWS / 128, OUTSZ / 128);
        sgemm128<<<grid, 256>>>(hsbuf, W_fc, b_fc, (const float*)nullptr, out,
                                HID, OUTSZ);
    }
}

// round 4
// speedup vs baseline: 1.0847x; 1.0847x over previous
#include <cuda_runtime.h>
#include <cstdint>

// ---------------------------------------------------------------------------
// Problem constants
// ---------------------------------------------------------------------------
#define T_STEPS 2048
#define BATCH   64
#define INSZ    512
#define HID     256
#define G4      1024      // 4*HID
#define OUTSZ   128
#define MROWS   (T_STEPS * BATCH)   // 131072

// Scratch (device globals: allocation-free per harness rules)
__device__ float g_Xp[(size_t)MROWS * G4];   // input projection + biases
__device__ float g_hs[(size_t)MROWS * HID];  // hidden states

// ---------------------------------------------------------------------------
// Packed fp32x2 FMA (SASS FFMA2) — used in the recurrence only.
// ---------------------------------------------------------------------------
__device__ __forceinline__ void ffma2(float2& d, const float2& a, const float2& b)
{
    asm("fma.rn.f32x2 %0, %1, %2, %0;"
        : "+l"(reinterpret_cast<unsigned long long&>(d))
        : "l"(reinterpret_cast<const unsigned long long&>(a)),
          "l"(reinterpret_cast<const unsigned long long&>(b)));
}

// ---------------------------------------------------------------------------
// 3xTF32 tensor-core GEMM (NT): C[m,n] = sum_k A[m,k]*B[n,k] + bias1[n](+bias2)
// BM=BN=128, BK=16, 256 threads (8 warps: 2x4 warp grid, warp tile 64x32).
// Each fp32 value split as x = hi(tf32) + lo(tf32); product uses
// hi*hi + hi*lo + lo*hi (AlBl term ~2^-22, dropped). hi/lo stored interleaved
// as float2 in smem so one 64-bit LDS feeds both operand splits.
// Requires M%128==0, N%128==0, K%16==0.
// ---------------------------------------------------------------------------
__device__ __forceinline__ float2 split_tf32(float x)
{
    uint32_t h;
    asm("cvt.rna.tf32.f32 %0, %1;" : "=r"(h) : "f"(x));
    float hf = __uint_as_float(h);
    float lo = x - hf;
    uint32_t l;
    asm("cvt.rna.tf32.f32 %0, %1;" : "=r"(l) : "f"(lo));
    return make_float2(hf, __uint_as_float(l));
}

#define MMA_TF32(d, a0, a1, a2, a3, b0, b1)                                   \
    asm("mma.sync.aligned.m16n8k8.row.col.f32.tf32.tf32.f32 "                  \
        "{%0,%1,%2,%3},{%4,%5,%6,%7},{%8,%9},{%0,%1,%2,%3};"                   \
        : "+f"((d)[0]), "+f"((d)[1]), "+f"((d)[2]), "+f"((d)[3])               \
        : "r"(a0), "r"(a1), "r"(a2), "r"(a3), "r"(b0), "r"(b1))

#define SPAD 18   // float2 row stride (16 K + 2 pad)

__global__ void __launch_bounds__(256)
tgemm128(const float* __restrict__ A, const float* __restrict__ Bm,
         const float* __restrict__ bias1, const float* __restrict__ bias2,
         float* __restrict__ C, int K, int N)
{
    __shared__ float2 As[128][SPAD];   // (hi, lo) pairs
    __shared__ float2 Bs[128][SPAD];

    const int tid  = threadIdx.x;
    const int lane = tid & 31;
    const int warp = tid >> 5;
    const int wm = warp & 1;           // 0..1  (64 rows of M each)
    const int wn = warp >> 1;          // 0..3  (32 cols of N each)
    const int g  = lane >> 2;          // 0..7
    const int t  = lane & 3;           // 0..3

    const size_t m0 = (size_t)blockIdx.x * 128;
    const int    n0 = blockIdx.y * 128;

    const int lrow = tid >> 1;         // 0..127
    const int lc   = (tid & 1) * 8;    // 0 or 8
    const float* Ag = A  + (m0 + lrow) * (size_t)K + lc;
    const float* Bg = Bm + (size_t)(n0 + lrow) * K + lc;

    float acc[4][4][4];
#pragma unroll
    for (int i = 0; i < 4; ++i)
#pragma unroll
        for (int j = 0; j < 4; ++j)
#pragma unroll
            for (int q = 0; q < 4; ++q) acc[i][j][q] = 0.f;

    for (int k0 = 0; k0 < K; k0 += 16) {
        float4 av0 = *(const float4*)(Ag + k0);
        float4 av1 = *(const float4*)(Ag + k0 + 4);
        float4 bv0 = *(const float4*)(Bg + k0);
        float4 bv1 = *(const float4*)(Bg + k0 + 4);
        __syncthreads();
        As[lrow][lc + 0] = split_tf32(av0.x);
        As[lrow][lc + 1] = split_tf32(av0.y);
        As[lrow][lc + 2] = split_tf32(av0.z);
        As[lrow][lc + 3] = split_tf32(av0.w);
        As[lrow][lc + 4] = split_tf32(av1.x);
        As[lrow][lc + 5] = split_tf32(av1.y);
        As[lrow][lc + 6] = split_tf32(av1.z);
        As[lrow][lc + 7] = split_tf32(av1.w);
        Bs[lrow][lc + 0] = split_tf32(bv0.x);
        Bs[lrow][lc + 1] = split_tf32(bv0.y);
        Bs[lrow][lc + 2] = split_tf32(bv0.z);
        Bs[lrow][lc + 3] = split_tf32(bv0.w);
        Bs[lrow][lc + 4] = split_tf32(bv1.x);
        Bs[lrow][lc + 5] = split_tf32(bv1.y);
        Bs[lrow][lc + 6] = split_tf32(bv1.z);
        Bs[lrow][lc + 7] = split_tf32(bv1.w);
        __syncthreads();

#pragma unroll
        for (int ks = 0; ks < 2; ++ks) {
            const int kb = ks * 8;
            uint32_t ah[4][4], al[4][4], bh[4][2], bl[4][2];
#pragma unroll
            for (int i = 0; i < 4; ++i) {
                int row = wm * 64 + i * 16 + g;
                float2 v00 = As[row][kb + t];
                float2 v10 = As[row + 8][kb + t];
                float2 v01 = As[row][kb + t + 4];
                float2 v11 = As[row + 8][kb + t + 4];
                ah[i][0] = __float_as_uint(v00.x);
                ah[i][1] = __float_as_uint(v10.x);
                ah[i][2] = __float_as_uint(v01.x);
                ah[i][3] = __float_as_uint(v11.x);
                al[i][0] = __float_as_uint(v00.y);
                al[i][1] = __float_as_uint(v10.y);
                al[i][2] = __float_as_uint(v01.y);
                al[i][3] = __float_as_uint(v11.y);
            }
#pragma unroll
            for (int j = 0; j < 4; ++j) {
                int n = wn * 32 + j * 8 + g;
                float2 w0 = Bs[n][kb + t];
                float2 w1 = Bs[n][kb + t + 4];
                bh[j][0] = __float_as_uint(w0.x);
                bh[j][1] = __float_as_uint(w1.x);
                bl[j][0] = __float_as_uint(w0.y);
                bl[j][1] = __float_as_uint(w1.y);
            }
#pragma unroll
            for (int i = 0; i < 4; ++i)
#pragma unroll
                for (int j = 0; j < 4; ++j) {
                    MMA_TF32(acc[i][j], ah[i][0], ah[i][1], ah[i][2], ah[i][3],
                             bh[j][0], bh[j][1]);
                    MMA_TF32(acc[i][j], ah[i][0], ah[i][1], ah[i][2], ah[i][3],
                             bl[j][0], bl[j][1]);
                    MMA_TF32(acc[i][j], al[i][0], al[i][1], al[i][2], al[i][3],
                             bh[j][0], bh[j][1]);
                }
        }
    }

    // Epilogue: bias + stores (float2 per fragment half-row).
#pragma unroll
    for (int j = 0; j < 4; ++j) {
        int col = n0 + wn * 32 + j * 8 + 2 * t;
        float b0 = bias1[col], b1 = bias1[col + 1];
        if (bias2) { b0 += bias2[col]; b1 += bias2[col + 1]; }
#pragma unroll
        for (int i = 0; i < 4; ++i) {
            size_t row = m0 + wm * 64 + i * 16 + g;
            *(float2*)(C + row * N + col) =
                make_float2(acc[i][j][0] + b0, acc[i][j][1] + b1);
            *(float2*)(C + (row + 8) * N + col) =
                make_float2(acc[i][j][2] + b0, acc[i][j][3] + b1);
        }
    }
}

// ---------------------------------------------------------------------------
// LSTM recurrence: persistent clustered kernel, register-resident weights.
// (unchanged from round 3 — it improved the recurrence ~1.5ms)
// ---------------------------------------------------------------------------
__global__ void __launch_bounds__(256, 1)
lstm_rec_kernel(const float* __restrict__ Whh,
                const float* __restrict__ Xp,
                float* __restrict__ hs)
{
    __shared__ float hsm[2][4][256];    // double-buffered h, [buf][b][k]
    __shared__ float part[8][4][128];   // [warp][b][lr]
    __shared__ float hstage[128];       // [b*32 + jj]

    const int tid  = threadIdx.x;
    const int lane = tid & 31;
    const int w    = tid >> 5;

    unsigned r;
    asm("mov.u32 %0, %%cluster_ctarank;" : "=r"(r));
    const int cl = blockIdx.x >> 3;

    // Load this thread's weights into registers: 4 rows x 16 k-pairs.
    float2 wreg[4][16];
#pragma unroll
    for (int rr = 0; rr < 4; ++rr) {
        int lr = lane * 4 + rr;
        int grow = ((lr >> 5) << 8) + (int)r * 32 + (lr & 31);
        const float2* wp = (const float2*)(Whh + (size_t)grow * 256 + w * 32);
#pragma unroll
        for (int k2 = 0; k2 < 16; ++k2) wreg[rr][k2] = wp[k2];
    }
    for (int i = tid; i < 4 * 256; i += 256) ((float*)hsm)[i] = 0.f; // h0 = 0
    __syncthreads();

    const int bb = tid >> 5;   // for tid<128: batch 0..3
    const int jj = tid & 31;
    float c = 0.f;             // cell state register (tid<128)

    for (int t = 0; t < T_STEPS; ++t) {
        const int cur = t & 1;

        // Early-issue Xp loads (hidden behind the dot loop)
        float xq0 = 0.f, xq1 = 0.f, xq2 = 0.f, xq3 = 0.f;
        if (tid < 128) {
            const float* xp = Xp + ((size_t)t * 64 + cl * 4 + bb) * 1024
                                 + (int)r * 32 + jj;
            xq0 = xp[0]; xq1 = xp[256]; xq2 = xp[512]; xq3 = xp[768];
        }

        // Dot phase: 16 k-pairs x 4 rows x 4 batches of FFMA2.
        float2 acc[4][4];
#pragma unroll
        for (int rr = 0; rr < 4; ++rr)
#pragma unroll
            for (int b = 0; b < 4; ++b) acc[rr][b] = make_float2(0.f, 0.f);

        const float* hb = &hsm[cur][0][w * 32];
#pragma unroll
        for (int k2 = 0; k2 < 16; ++k2) {
            float2 h0 = *(const float2*)(hb + 2 * k2);
            float2 h1 = *(const float2*)(hb + 256 + 2 * k2);
            float2 h2 = *(const float2*)(hb + 512 + 2 * k2);
            float2 h3 = *(const float2*)(hb + 768 + 2 * k2);
#pragma unroll
            for (int rr = 0; rr < 4; ++rr) {
                ffma2(acc[rr][0], wreg[rr][k2], h0);
                ffma2(acc[rr][1], wreg[rr][k2], h1);
                ffma2(acc[rr][2], wreg[rr][k2], h2);
                ffma2(acc[rr][3], wreg[rr][k2], h3);
            }
        }
        // Horizontal add (even+odd K sums) and store partials.
#pragma unroll
        for (int b = 0; b < 4; ++b) {
            float4 v = make_float4(acc[0][b].x + acc[0][b].y,
                                   acc[1][b].x + acc[1][b].y,
                                   acc[2][b].x + acc[2][b].y,
                                   acc[3][b].x + acc[3][b].y);
            *(float4*)&part[w][b][lane * 4] = v;
        }
        __syncthreads();

        // Reduction + gates (tid<128: one (jj, bb) pair each)
        if (tid < 128) {
            float s0 = xq0, s1 = xq1, s2 = xq2, s3 = xq3;
#pragma unroll
            for (int w8 = 0; w8 < 8; ++w8) {
                const float* p = &part[w8][bb][jj];
                s0 += p[0]; s1 += p[32]; s2 += p[64]; s3 += p[96];
            }
            float ig = 1.f / (1.f + __expf(-s0));
            float fg = 1.f / (1.f + __expf(-s1));
            float e2 = __expf(2.f * s2);
            float gg = (e2 - 1.f) / (e2 + 1.f);
            float og = 1.f / (1.f + __expf(-s3));
            c = fg * c + ig * gg;
            float ec = __expf(2.f * c);
            float h = og * ((ec - 1.f) / (ec + 1.f));
            hstage[bb * 32 + jj] = h;
            hs[((size_t)t * 64 + cl * 4 + bb) * 256 + (int)r * 32 + jj] = h;
        }
        __syncthreads();

        // DSMEM push: broadcast this CTA's 128 new h values into every
        // cluster CTA's hsm[next]. One STS.128 per thread (8 dst x 32 f4).
        {
            const int nxt = cur ^ 1;
            const unsigned dst = (unsigned)(tid >> 5);   // 0..7
            const int q = tid & 31;                      // float4 idx over 128
            float4 v = ((const float4*)hstage)[q];
            float* dp = &hsm[nxt][q >> 3][(int)r * 32 + ((q & 7) << 2)];
            unsigned la = (unsigned)__cvta_generic_to_shared(dp);
            unsigned ra;
            asm volatile("mapa.shared::cluster.u32 %0, %1, %2;"
                         : "=r"(ra) : "r"(la), "r"(dst));
            asm volatile("st.shared::cluster.v4.f32 [%0], {%1,%2,%3,%4};"
                         :: "r"(ra), "f"(v.x), "f"(v.y), "f"(v.z), "f"(v.w)
                         : "memory");
        }
        asm volatile("barrier.cluster.arrive.aligned;" ::: "memory");
        asm volatile("barrier.cluster.wait.aligned;"   ::: "memory");
    }
}

// ---------------------------------------------------------------------------
// Launch
// ---------------------------------------------------------------------------
extern "C" void kernel_launch(void* const* d_in, const int* in_sizes, int n_in,
                              void* d_out, int out_size)
{
    const float* inputs = (const float*)d_in[0];
    const float* W_ih   = (const float*)d_in[1];
    const float* W_hh   = (const float*)d_in[2];
    const float* b_ih   = (const float*)d_in[3];
    const float* b_hh   = (const float*)d_in[4];
    const float* W_fc   = (const float*)d_in[5];
    const float* b_fc   = (const float*)d_in[6];
    float* out = (float*)d_out;

    float *Xp, *hsbuf;
    cudaGetSymbolAddress((void**)&Xp, g_Xp);
    cudaGetSymbolAddress((void**)&hsbuf, g_hs);

    // 1) Xp = inputs @ W_ih^T + (b_ih + b_hh)   [131072 x 1024], 3xTF32
    {
        dim3 grid(MROWS / 128, G4 / 128);
        tgemm128<<<grid, 256>>>(inputs, W_ih, b_ih, b_hh, Xp, INSZ, G4);
    }

    // 2) LSTM recurrence (clustered persistent kernel) -> hs [131072 x 256]
    {
        cudaLaunchConfig_t cfg = {};
        cfg.gridDim = dim3(128, 1, 1);
        cfg.blockDim = dim3(256, 1, 1);
        cfg.dynamicSmemBytes = 0;
        cfg.stream = 0;
        cudaLaunchAttribute attr[1];
        attr[0].id = cudaLaunchAttributeClusterDimension;
        attr[0].val.clusterDim.x = 8;
        attr[0].val.clusterDim.y = 1;
        attr[0].val.clusterDim.z = 1;
        cfg.attrs = attr;
        cfg.numAttrs = 1;
        cudaLaunchKernelEx(&cfg, lstm_rec_kernel, W_hh, (const float*)Xp, hsbuf);
    }

    // 3) out = hs @ W_fc^T + b_fc   [131072 x 128], 3xTF32
    {
        dim3 grid(MROWS / 128, OUTSZ / 128);
        tgemm128<<<grid, 256>>>(hsbuf, W_fc, b_fc, (const float*)nullptr, out,
                                HID, OUTSZ);
    }
}